// round 1
// baseline (speedup 1.0000x reference)
#include <cuda_runtime.h>
#include <math.h>

#define NTH 256
#define TW  128           // outputs per block

constexpr int NTOT = 2097152;
constexpr int NOUT = NTOT - 6;
constexpr int ST   = 136; // activation row stride (positions per channel row)

// ---- shared-memory float offsets ----
constexpr int O_W1 = 0;            // 100
constexpr int O_B1 = O_W1 + 100;   // 20
constexpr int O_W2 = O_B1 + 20;    // 4000
constexpr int O_B2 = O_W2 + 4000;  // 40
constexpr int O_W3 = O_B2 + 40;    // 3200
constexpr int O_B3 = O_W3 + 3200;  // 80
constexpr int O_W4 = O_B3 + 80;    // 3200
constexpr int O_B4 = O_W4 + 3200;  // 40
constexpr int O_W5 = O_B4 + 40;    // 2400
constexpr int O_B5 = O_W5 + 2400;  // 20
constexpr int O_W6 = O_B5 + 20;    // 20
constexpr int O_B6 = O_W6 + 20;    // 1
constexpr int O_UU  = O_B6 + 1;        // 144  (uu window: [o0-4, o0+TW+10))
constexpr int O_DIF = O_UU  + 144;     // 144  (dif window: [o0-3, o0+TW+9))
constexpr int O_A1  = O_DIF + 144;     // 20*ST  (positions base o0-1, width TW+8)
constexpr int O_A2  = O_A1  + 20*ST;   // 40*ST  (base o0+1, width TW+4)
constexpr int O_A3  = O_A2  + 40*ST;   // 80*ST  (base o0+1)
constexpr int O_A4  = O_A3  + 80*ST;   // 40*ST  (base o0+1)
constexpr int O_A5  = O_A4  + 40*ST;   // 20*ST  (base o0+2, width TW+2 valid)
constexpr int O_BM  = O_A5  + 20*ST;   // ST     (base o0+2, width TW+2 valid)
constexpr int SMEM_FLOATS = O_BM + ST;
constexpr int SMEM_BYTES  = SMEM_FLOATS * 4;

__device__ __forceinline__ float eluf(float x) {
    return x > 0.f ? x : expm1f(x);
}

// One WENO side: u0..u4 are the 5-point stencil, m0..m2 the learned beta multipliers.
__device__ __forceinline__ float weno_side(float u0, float u1, float u2, float u3, float u4,
                                           float m0, float m1, float m2, float e) {
    const float c16 = 1.f / 6.f;
    float f0 = (11.f * u2 - 7.f * u3 + 2.f * u4) * c16;
    float f1 = (2.f * u1 + 5.f * u2 - u3) * c16;
    float f2 = (-u0 + 5.f * u1 + 2.f * u2) * c16;
    float t, b0, b1, b2;
    t = u2 - 2.f * u3 + u4;          b0 = (13.f / 12.f) * t * t;
    t = 3.f * u2 - 4.f * u3 + u4;    b0 += 0.25f * t * t;
    t = u1 - 2.f * u2 + u3;          b1 = (13.f / 12.f) * t * t;
    t = u1 - u3;                     b1 += 0.25f * t * t;
    t = u0 - 2.f * u1 + u2;          b2 = (13.f / 12.f) * t * t;
    t = u0 - 4.f * u1 + 3.f * u2;    b2 += 0.25f * t * t;
    b0 *= m0; b1 *= m1; b2 *= m2;
    float brs = (b2 - b0) * (b2 - b0);
    float q0 = (e + b0) * (e + b0);
    float q1 = (e + b1) * (e + b1);
    float q2 = (e + b2) * (e + b2);
    float o0 = 0.1f / q0 * (brs + q0);
    float o1 = 0.6f / q1 * (brs + q1);
    float o2 = 0.3f / q2 * (brs + q2);
    float s = o0 + o1 + o2;
    return (o0 * f0 + o1 * f1 + o2 * f2) / s;
}

__global__ __launch_bounds__(NTH)
void weno_fused(const float* __restrict__ uu, const float* __restrict__ e_p,
                const float* __restrict__ w1, const float* __restrict__ b1,
                const float* __restrict__ w2, const float* __restrict__ b2,
                const float* __restrict__ w3, const float* __restrict__ b3,
                const float* __restrict__ w4, const float* __restrict__ b4,
                const float* __restrict__ w5, const float* __restrict__ b5,
                const float* __restrict__ w6, const float* __restrict__ b6,
                float* __restrict__ out) {
    extern __shared__ float sm[];
    const int tid = threadIdx.x;
    const int o0 = blockIdx.x * TW;

    // ---- stage weights ----
    for (int i = tid; i < 100;  i += NTH) sm[O_W1 + i] = w1[i];
    for (int i = tid; i < 20;   i += NTH) sm[O_B1 + i] = b1[i];
    for (int i = tid; i < 4000; i += NTH) sm[O_W2 + i] = w2[i];
    for (int i = tid; i < 40;   i += NTH) sm[O_B2 + i] = b2[i];
    for (int i = tid; i < 3200; i += NTH) sm[O_W3 + i] = w3[i];
    for (int i = tid; i < 80;   i += NTH) sm[O_B3 + i] = b3[i];
    for (int i = tid; i < 3200; i += NTH) sm[O_W4 + i] = w4[i];
    for (int i = tid; i < 40;   i += NTH) sm[O_B4 + i] = b4[i];
    for (int i = tid; i < 2400; i += NTH) sm[O_W5 + i] = w5[i];
    for (int i = tid; i < 20;   i += NTH) sm[O_B5 + i] = b5[i];
    for (int i = tid; i < 20;   i += NTH) sm[O_W6 + i] = w6[i];
    if (tid == 0) sm[O_B6] = b6[0];

    // ---- stage uu window [o0-4, o0+TW+10), index-clamped ----
    for (int i = tid; i < TW + 14; i += NTH) {
        int g = o0 - 4 + i;
        g = min(max(g, 0), NTOT - 1);
        sm[O_UU + i] = uu[g];
    }
    __syncthreads();

    // ---- dif window [o0-3, o0+TW+9); zero outside [0,N) (conv zero-padding) ----
    for (int i = tid; i < TW + 12; i += NTH) {
        int gi = o0 - 3 + i;
        float v = 0.f;
        if ((unsigned)gi < (unsigned)NTOT) {
            int m1 = min(gi, NTOT - 2);
            int m2 = max(gi - 1, 0);
            int base = o0 - 4;
            v = 0.5f * ((sm[O_UU + m1 + 1 - base] - sm[O_UU + m1 - base]) +
                        (sm[O_UU + m2 + 1 - base] - sm[O_UU + m2 - base]));
        }
        sm[O_DIF + i] = v;
    }
    __syncthreads();

    // ---- conv1: 1->20, k5 pad2.  a1 positions base o0-1, width 136 ----
    for (int t = tid; t < 20 * 34; t += NTH) {
        int c = t / 34, x0 = (t % 34) * 4;
        const float* wr = &sm[O_W1 + c * 5];
        float bias = sm[O_B1 + c];
        float c0 = bias, c1 = bias, c2 = bias, c3 = bias;
        float win[8];
        #pragma unroll
        for (int i = 0; i < 8; i++) win[i] = sm[O_DIF + x0 + i];
        #pragma unroll
        for (int k = 0; k < 5; k++) {
            float w = wr[k];
            c0 += w * win[k]; c1 += w * win[k + 1];
            c2 += w * win[k + 2]; c3 += w * win[k + 3];
        }
        int p = o0 - 1 + x0;
        float* dst = &sm[O_A1 + c * ST + x0];
        dst[0] = (unsigned)(p + 0) < (unsigned)NTOT ? eluf(c0) : 0.f;
        dst[1] = (unsigned)(p + 1) < (unsigned)NTOT ? eluf(c1) : 0.f;
        dst[2] = (unsigned)(p + 2) < (unsigned)NTOT ? eluf(c2) : 0.f;
        dst[3] = (unsigned)(p + 3) < (unsigned)NTOT ? eluf(c3) : 0.f;
    }
    __syncthreads();

    // ---- conv2: 20->40, k5 pad2.  a2 positions base o0+1, width 132 ----
    for (int t = tid; t < 40 * 33; t += NTH) {
        int oc = t / 33, x0 = (t % 33) * 4;
        const float* wr = &sm[O_W2 + oc * 100];
        float bias = sm[O_B2 + oc];
        float c0 = bias, c1 = bias, c2 = bias, c3 = bias;
        #pragma unroll
        for (int ic = 0; ic < 20; ic++) {
            const float* ar = &sm[O_A1 + ic * ST + x0];
            float win[8];
            #pragma unroll
            for (int i = 0; i < 8; i++) win[i] = ar[i];
            #pragma unroll
            for (int k = 0; k < 5; k++) {
                float w = wr[ic * 5 + k];
                c0 += w * win[k]; c1 += w * win[k + 1];
                c2 += w * win[k + 2]; c3 += w * win[k + 3];
            }
        }
        float* dst = &sm[O_A2 + oc * ST + x0];
        dst[0] = eluf(c0); dst[1] = eluf(c1); dst[2] = eluf(c2); dst[3] = eluf(c3);
    }
    __syncthreads();

    // ---- conv3: 40->80, 1x1.  2 output channels per task ----
    for (int t = tid; t < 40 * 33; t += NTH) {
        int ocp = t / 33, x0 = (t % 33) * 4;
        int oc0 = 2 * ocp;
        const float* wA = &sm[O_W3 + oc0 * 40];
        const float* wB = wA + 40;
        float bA = sm[O_B3 + oc0], bB = sm[O_B3 + oc0 + 1];
        float A0 = bA, A1 = bA, A2 = bA, A3 = bA;
        float B0 = bB, B1 = bB, B2 = bB, B3 = bB;
        #pragma unroll 8
        for (int ic = 0; ic < 40; ic++) {
            const float* ar = &sm[O_A2 + ic * ST + x0];
            float v0 = ar[0], v1 = ar[1], v2 = ar[2], v3 = ar[3];
            float a = wA[ic], b = wB[ic];
            A0 += a * v0; A1 += a * v1; A2 += a * v2; A3 += a * v3;
            B0 += b * v0; B1 += b * v1; B2 += b * v2; B3 += b * v3;
        }
        float* dA = &sm[O_A3 + oc0 * ST + x0];
        float* dB = dA + ST;
        dA[0] = eluf(A0); dA[1] = eluf(A1); dA[2] = eluf(A2); dA[3] = eluf(A3);
        dB[0] = eluf(B0); dB[1] = eluf(B1); dB[2] = eluf(B2); dB[3] = eluf(B3);
    }
    __syncthreads();

    // ---- conv4: 80->40, 1x1.  2 output channels per task; zero outside [0,N) ----
    for (int t = tid; t < 20 * 33; t += NTH) {
        int ocp = t / 33, x0 = (t % 33) * 4;
        int oc0 = 2 * ocp;
        const float* wA = &sm[O_W4 + oc0 * 80];
        const float* wB = wA + 80;
        float bA = sm[O_B4 + oc0], bB = sm[O_B4 + oc0 + 1];
        float A0 = bA, A1 = bA, A2 = bA, A3 = bA;
        float B0 = bB, B1 = bB, B2 = bB, B3 = bB;
        #pragma unroll 8
        for (int ic = 0; ic < 80; ic++) {
            const float* ar = &sm[O_A3 + ic * ST + x0];
            float v0 = ar[0], v1 = ar[1], v2 = ar[2], v3 = ar[3];
            float a = wA[ic], b = wB[ic];
            A0 += a * v0; A1 += a * v1; A2 += a * v2; A3 += a * v3;
            B0 += b * v0; B1 += b * v1; B2 += b * v2; B3 += b * v3;
        }
        int p = o0 + 1 + x0;
        float* dA = &sm[O_A4 + oc0 * ST + x0];
        float* dB = dA + ST;
        dA[0] = (unsigned)(p + 0) < (unsigned)NTOT ? eluf(A0) : 0.f;
        dA[1] = (unsigned)(p + 1) < (unsigned)NTOT ? eluf(A1) : 0.f;
        dA[2] = (unsigned)(p + 2) < (unsigned)NTOT ? eluf(A2) : 0.f;
        dA[3] = (unsigned)(p + 3) < (unsigned)NTOT ? eluf(A3) : 0.f;
        dB[0] = (unsigned)(p + 0) < (unsigned)NTOT ? eluf(B0) : 0.f;
        dB[1] = (unsigned)(p + 1) < (unsigned)NTOT ? eluf(B1) : 0.f;
        dB[2] = (unsigned)(p + 2) < (unsigned)NTOT ? eluf(B2) : 0.f;
        dB[3] = (unsigned)(p + 3) < (unsigned)NTOT ? eluf(B3) : 0.f;
    }
    // zero a4 tail slots (read by conv5 sliding window at the tile edge)
    for (int t = tid; t < 40; t += NTH) {
        float* r = &sm[O_A4 + t * ST];
        r[132] = 0.f; r[133] = 0.f; r[134] = 0.f; r[135] = 0.f;
    }
    __syncthreads();

    // ---- conv5: 40->20, k3 pad1.  a5 positions base o0+2 ----
    for (int t = tid; t < 20 * 33; t += NTH) {
        int oc = t / 33, x0 = (t % 33) * 4;
        const float* wr = &sm[O_W5 + oc * 120];
        float bias = sm[O_B5 + oc];
        float c0 = bias, c1 = bias, c2 = bias, c3 = bias;
        #pragma unroll 8
        for (int ic = 0; ic < 40; ic++) {
            const float* ar = &sm[O_A4 + ic * ST + x0];
            float win[6];
            #pragma unroll
            for (int i = 0; i < 6; i++) win[i] = ar[i];
            #pragma unroll
            for (int k = 0; k < 3; k++) {
                float w = wr[ic * 3 + k];
                c0 += w * win[k]; c1 += w * win[k + 1];
                c2 += w * win[k + 2]; c3 += w * win[k + 3];
            }
        }
        float* dst = &sm[O_A5 + oc * ST + x0];
        dst[0] = eluf(c0); dst[1] = eluf(c1); dst[2] = eluf(c2); dst[3] = eluf(c3);
    }
    __syncthreads();

    // ---- conv6 + sigmoid + bias: beta_mult, base o0+2, width TW+2 ----
    for (int x = tid; x < TW + 2; x += NTH) {
        float acc = sm[O_B6];
        #pragma unroll
        for (int c = 0; c < 20; c++) acc += sm[O_W6 + c] * sm[O_A5 + c * ST + x];
        sm[O_BM + x] = 1.f / (1.f + expf(-acc)) + 0.1f;
    }
    __syncthreads();

    // ---- WENO5 flux ----
    int j = o0 + tid;
    if (tid < TW && j < NOUT) {
        const float* U = &sm[O_UU + tid + 5];   // uu[j+1 .. j+6]
        float v0 = U[0], v1 = U[1], v2 = U[2], v3 = U[3], v4 = U[4], v5 = U[5];
        float m0 = sm[O_BM + tid];
        float m1 = sm[O_BM + tid + 1];
        float m2 = sm[O_BM + tid + 2];
        float e = e_p[0];
        float fluxp = weno_side(v1, v2, v3, v4, v5, m0, m1, m2, e);
        float fluxn = weno_side(v0, v1, v2, v3, v4, m0, m1, m2, e);
        out[j] = fluxp - fluxn;
    }
}

extern "C" void kernel_launch(void* const* d_in, const int* in_sizes, int n_in,
                              void* d_out, int out_size) {
    const float* uu = (const float*)d_in[0];
    const float* e  = (const float*)d_in[1];
    const float* w1 = (const float*)d_in[2];
    const float* b1 = (const float*)d_in[3];
    const float* w2 = (const float*)d_in[4];
    const float* b2 = (const float*)d_in[5];
    const float* w3 = (const float*)d_in[6];
    const float* b3 = (const float*)d_in[7];
    const float* w4 = (const float*)d_in[8];
    const float* b4 = (const float*)d_in[9];
    const float* w5 = (const float*)d_in[10];
    const float* b5 = (const float*)d_in[11];
    const float* w6 = (const float*)d_in[12];
    const float* b6 = (const float*)d_in[13];
    float* out = (float*)d_out;

    cudaFuncSetAttribute(weno_fused, cudaFuncAttributeMaxDynamicSharedMemorySize, SMEM_BYTES);
    int grid = (NOUT + TW - 1) / TW;
    weno_fused<<<grid, NTH, SMEM_BYTES>>>(uu, e, w1, b1, w2, b2, w3, b3, w4, b4,
                                          w5, b5, w6, b6, out);
}

// round 2
// speedup vs baseline: 1.7775x; 1.7775x over previous
#include <cuda_runtime.h>
#include <math.h>

#define NTH 256
#define TW  128           // outputs per block

constexpr int NTOT = 2097152;
constexpr int NOUT = NTOT - 6;
constexpr int ST   = 136; // activation row stride (floats), 16B-aligned

// ---- shared-memory float offsets ----
constexpr int O_W1 = 0;            // 100
constexpr int O_B1 = 100;          // 20
constexpr int O_W2 = 120;          // 4000
constexpr int O_B2 = 4120;         // 40
constexpr int O_W3 = 4160;         // 3200
constexpr int O_B3 = 7360;         // 80
constexpr int O_W4 = 7440;         // 3200
constexpr int O_B4 = 10640;        // 40
constexpr int O_W5 = 10680;        // 2400
constexpr int O_B5 = 13080;        // 20
constexpr int O_W6 = 13100;        // 20
constexpr int O_B6 = 13120;        // 1 (+3 pad for 16B alignment)
constexpr int O_UU  = 13124;       // 144  (uu window: [o0-4, o0+TW+10))
constexpr int O_DIF = 13268;       // 144  (dif window: [o0-3, o0+TW+9))
constexpr int O_A1  = 13412;       // 20*ST  (base o0-1)
constexpr int O_A2  = O_A1 + 20*ST; // 40*ST (base o0+1)
constexpr int O_A3  = O_A2 + 40*ST; // 80*ST (base o0+1)
constexpr int O_A4  = O_A3 + 80*ST; // 40*ST (base o0+1)
constexpr int O_A5  = O_A4 + 40*ST; // 20*ST (base o0+2)
constexpr int O_BM  = O_A5 + 20*ST; // ST    (base o0+2)
constexpr int SMEM_FLOATS = O_BM + ST;
constexpr int SMEM_BYTES  = SMEM_FLOATS * 4;

__device__ __forceinline__ float eluf(float x) {
    return x > 0.f ? x : (__expf(x) - 1.f);
}

__device__ __forceinline__ float weno_side(float u0, float u1, float u2, float u3, float u4,
                                           float m0, float m1, float m2, float e) {
    const float c16 = 1.f / 6.f;
    float f0 = (11.f * u2 - 7.f * u3 + 2.f * u4) * c16;
    float f1 = (2.f * u1 + 5.f * u2 - u3) * c16;
    float f2 = (-u0 + 5.f * u1 + 2.f * u2) * c16;
    float t, b0, b1, b2;
    t = u2 - 2.f * u3 + u4;          b0 = (13.f / 12.f) * t * t;
    t = 3.f * u2 - 4.f * u3 + u4;    b0 += 0.25f * t * t;
    t = u1 - 2.f * u2 + u3;          b1 = (13.f / 12.f) * t * t;
    t = u1 - u3;                     b1 += 0.25f * t * t;
    t = u0 - 2.f * u1 + u2;          b2 = (13.f / 12.f) * t * t;
    t = u0 - 4.f * u1 + 3.f * u2;    b2 += 0.25f * t * t;
    b0 *= m0; b1 *= m1; b2 *= m2;
    float brs = (b2 - b0) * (b2 - b0);
    float q0 = (e + b0) * (e + b0);
    float q1 = (e + b1) * (e + b1);
    float q2 = (e + b2) * (e + b2);
    float o0 = 0.1f / q0 * (brs + q0);
    float o1 = 0.6f / q1 * (brs + q1);
    float o2 = 0.3f / q2 * (brs + q2);
    float s = o0 + o1 + o2;
    return (o0 * f0 + o1 * f1 + o2 * f2) / s;
}

__global__ __launch_bounds__(NTH)
void weno_fused(const float* __restrict__ uu, const float* __restrict__ e_p,
                const float* __restrict__ w1, const float* __restrict__ b1,
                const float* __restrict__ w2, const float* __restrict__ b2,
                const float* __restrict__ w3, const float* __restrict__ b3,
                const float* __restrict__ w4, const float* __restrict__ b4,
                const float* __restrict__ w5, const float* __restrict__ b5,
                const float* __restrict__ w6, const float* __restrict__ b6,
                float* __restrict__ out) {
    extern __shared__ float sm[];
    const int tid = threadIdx.x;
    const int o0 = blockIdx.x * TW;

    // ---- stage weights ----
    for (int i = tid; i < 100;  i += NTH) sm[O_W1 + i] = w1[i];
    for (int i = tid; i < 20;   i += NTH) sm[O_B1 + i] = b1[i];
    for (int i = tid; i < 4000; i += NTH) sm[O_W2 + i] = w2[i];
    for (int i = tid; i < 40;   i += NTH) sm[O_B2 + i] = b2[i];
    for (int i = tid; i < 3200; i += NTH) sm[O_W3 + i] = w3[i];
    for (int i = tid; i < 80;   i += NTH) sm[O_B3 + i] = b3[i];
    for (int i = tid; i < 3200; i += NTH) sm[O_W4 + i] = w4[i];
    for (int i = tid; i < 40;   i += NTH) sm[O_B4 + i] = b4[i];
    for (int i = tid; i < 2400; i += NTH) sm[O_W5 + i] = w5[i];
    for (int i = tid; i < 20;   i += NTH) sm[O_B5 + i] = b5[i];
    for (int i = tid; i < 20;   i += NTH) sm[O_W6 + i] = w6[i];
    if (tid == 0) sm[O_B6] = b6[0];

    // ---- stage uu window [o0-4, o0+TW+10), index-clamped ----
    for (int i = tid; i < TW + 14; i += NTH) {
        int g = o0 - 4 + i;
        g = min(max(g, 0), NTOT - 1);
        sm[O_UU + i] = uu[g];
    }
    __syncthreads();

    // ---- dif window [o0-3, o0+TW+9); zero outside [0,N) ----
    for (int i = tid; i < TW + 12; i += NTH) {
        int gi = o0 - 3 + i;
        float v = 0.f;
        if ((unsigned)gi < (unsigned)NTOT) {
            int m1 = min(gi, NTOT - 2);
            int m2 = max(gi - 1, 0);
            int base = o0 - 4;
            v = 0.5f * ((sm[O_UU + m1 + 1 - base] - sm[O_UU + m1 - base]) +
                        (sm[O_UU + m2 + 1 - base] - sm[O_UU + m2 - base]));
        }
        sm[O_DIF + i] = v;
    }
    __syncthreads();

    // ---- conv1: 1->20, k5 pad2.  a1 base o0-1, width 136 (34 quads) ----
    for (int t = tid; t < 20 * 34; t += NTH) {
        int c = t / 34, x0 = (t % 34) * 4;
        const float* wr = &sm[O_W1 + c * 5];
        float bias = sm[O_B1 + c];
        float c0 = bias, c1 = bias, c2 = bias, c3 = bias;
        float4 d0 = *(const float4*)&sm[O_DIF + x0];
        float4 d1 = *(const float4*)&sm[O_DIF + x0 + 4];
        float win[8] = {d0.x, d0.y, d0.z, d0.w, d1.x, d1.y, d1.z, d1.w};
        #pragma unroll
        for (int k = 0; k < 5; k++) {
            float w = wr[k];
            c0 += w * win[k]; c1 += w * win[k + 1];
            c2 += w * win[k + 2]; c3 += w * win[k + 3];
        }
        int p = o0 - 1 + x0;
        float4 r;
        r.x = (unsigned)(p + 0) < (unsigned)NTOT ? eluf(c0) : 0.f;
        r.y = (unsigned)(p + 1) < (unsigned)NTOT ? eluf(c1) : 0.f;
        r.z = (unsigned)(p + 2) < (unsigned)NTOT ? eluf(c2) : 0.f;
        r.w = (unsigned)(p + 3) < (unsigned)NTOT ? eluf(c3) : 0.f;
        *(float4*)&sm[O_A1 + c * ST + x0] = r;
    }
    __syncthreads();

    // ---- conv2: 20->40, k5 pad2.  2 oc x 8 pos per task.  base o0+1 ----
    for (int t = tid; t < 20 * 17; t += NTH) {
        int ocp = t / 17, oct = t % 17;
        int x0 = oct * 8;
        int oc0 = ocp * 2;
        const float* wA = &sm[O_W2 + oc0 * 100];
        const float* wB = wA + 100;
        float bA = sm[O_B2 + oc0], bB = sm[O_B2 + oc0 + 1];
        float aA[8], aB[8];
        #pragma unroll
        for (int p = 0; p < 8; p++) { aA[p] = bA; aB[p] = bB; }
        #pragma unroll 4
        for (int ic = 0; ic < 20; ic++) {
            const float* ar = &sm[O_A1 + ic * ST + x0];
            float4 v0 = *(const float4*)(ar);
            float4 v1 = *(const float4*)(ar + 4);
            float4 v2 = *(const float4*)(ar + 8);
            float win[12] = {v0.x, v0.y, v0.z, v0.w, v1.x, v1.y, v1.z, v1.w,
                             v2.x, v2.y, v2.z, v2.w};
            #pragma unroll
            for (int k = 0; k < 5; k++) {
                float a = wA[ic * 5 + k], b = wB[ic * 5 + k];
                #pragma unroll
                for (int p = 0; p < 8; p++) {
                    aA[p] += a * win[p + k];
                    aB[p] += b * win[p + k];
                }
            }
        }
        float* dA = &sm[O_A2 + oc0 * ST + x0];
        float* dB = dA + ST;
        float4 rA0, rA1, rB0, rB1;
        rA0.x = eluf(aA[0]); rA0.y = eluf(aA[1]); rA0.z = eluf(aA[2]); rA0.w = eluf(aA[3]);
        rA1.x = eluf(aA[4]); rA1.y = eluf(aA[5]); rA1.z = eluf(aA[6]); rA1.w = eluf(aA[7]);
        rB0.x = eluf(aB[0]); rB0.y = eluf(aB[1]); rB0.z = eluf(aB[2]); rB0.w = eluf(aB[3]);
        rB1.x = eluf(aB[4]); rB1.y = eluf(aB[5]); rB1.z = eluf(aB[6]); rB1.w = eluf(aB[7]);
        *(float4*)(dA) = rA0; *(float4*)(dA + 4) = rA1;
        *(float4*)(dB) = rB0; *(float4*)(dB + 4) = rB1;
    }
    __syncthreads();

    // ---- conv3: 40->80, 1x1.  4 oc x 4 pos per task ----
    for (int t = tid; t < 20 * 33; t += NTH) {
        int ocq = t / 33, xq = t % 33;
        int x0 = xq * 4;
        int oc0 = ocq * 4;
        float a0[4], a1[4], a2[4], a3[4];
        {
            float q0 = sm[O_B3 + oc0], q1 = sm[O_B3 + oc0 + 1];
            float q2 = sm[O_B3 + oc0 + 2], q3 = sm[O_B3 + oc0 + 3];
            #pragma unroll
            for (int p = 0; p < 4; p++) { a0[p] = q0; a1[p] = q1; a2[p] = q2; a3[p] = q3; }
        }
        #pragma unroll 8
        for (int ic = 0; ic < 40; ic++) {
            float4 v = *(const float4*)&sm[O_A2 + ic * ST + x0];
            float w0 = sm[O_W3 + (oc0 + 0) * 40 + ic];
            float w1_ = sm[O_W3 + (oc0 + 1) * 40 + ic];
            float w2_ = sm[O_W3 + (oc0 + 2) * 40 + ic];
            float w3_ = sm[O_W3 + (oc0 + 3) * 40 + ic];
            a0[0] += w0 * v.x; a0[1] += w0 * v.y; a0[2] += w0 * v.z; a0[3] += w0 * v.w;
            a1[0] += w1_ * v.x; a1[1] += w1_ * v.y; a1[2] += w1_ * v.z; a1[3] += w1_ * v.w;
            a2[0] += w2_ * v.x; a2[1] += w2_ * v.y; a2[2] += w2_ * v.z; a2[3] += w2_ * v.w;
            a3[0] += w3_ * v.x; a3[1] += w3_ * v.y; a3[2] += w3_ * v.z; a3[3] += w3_ * v.w;
        }
        float* d0 = &sm[O_A3 + oc0 * ST + x0];
        float4 r;
        r.x = eluf(a0[0]); r.y = eluf(a0[1]); r.z = eluf(a0[2]); r.w = eluf(a0[3]);
        *(float4*)(d0) = r;
        r.x = eluf(a1[0]); r.y = eluf(a1[1]); r.z = eluf(a1[2]); r.w = eluf(a1[3]);
        *(float4*)(d0 + ST) = r;
        r.x = eluf(a2[0]); r.y = eluf(a2[1]); r.z = eluf(a2[2]); r.w = eluf(a2[3]);
        *(float4*)(d0 + 2 * ST) = r;
        r.x = eluf(a3[0]); r.y = eluf(a3[1]); r.z = eluf(a3[2]); r.w = eluf(a3[3]);
        *(float4*)(d0 + 3 * ST) = r;
    }
    __syncthreads();

    // ---- conv4: 80->40, 1x1.  4 oc x 4 pos per task; zero outside [0,N) ----
    for (int t = tid; t < 10 * 33; t += NTH) {
        int ocq = t / 33, xq = t % 33;
        int x0 = xq * 4;
        int oc0 = ocq * 4;
        float a0[4], a1[4], a2[4], a3[4];
        {
            float q0 = sm[O_B4 + oc0], q1 = sm[O_B4 + oc0 + 1];
            float q2 = sm[O_B4 + oc0 + 2], q3 = sm[O_B4 + oc0 + 3];
            #pragma unroll
            for (int p = 0; p < 4; p++) { a0[p] = q0; a1[p] = q1; a2[p] = q2; a3[p] = q3; }
        }
        #pragma unroll 8
        for (int ic = 0; ic < 80; ic++) {
            float4 v = *(const float4*)&sm[O_A3 + ic * ST + x0];
            float w0 = sm[O_W4 + (oc0 + 0) * 80 + ic];
            float w1_ = sm[O_W4 + (oc0 + 1) * 80 + ic];
            float w2_ = sm[O_W4 + (oc0 + 2) * 80 + ic];
            float w3_ = sm[O_W4 + (oc0 + 3) * 80 + ic];
            a0[0] += w0 * v.x; a0[1] += w0 * v.y; a0[2] += w0 * v.z; a0[3] += w0 * v.w;
            a1[0] += w1_ * v.x; a1[1] += w1_ * v.y; a1[2] += w1_ * v.z; a1[3] += w1_ * v.w;
            a2[0] += w2_ * v.x; a2[1] += w2_ * v.y; a2[2] += w2_ * v.z; a2[3] += w2_ * v.w;
            a3[0] += w3_ * v.x; a3[1] += w3_ * v.y; a3[2] += w3_ * v.z; a3[3] += w3_ * v.w;
        }
        int p0 = o0 + 1 + x0;
        float m0 = (unsigned)(p0 + 0) < (unsigned)NTOT ? 1.f : 0.f;
        float m1 = (unsigned)(p0 + 1) < (unsigned)NTOT ? 1.f : 0.f;
        float m2 = (unsigned)(p0 + 2) < (unsigned)NTOT ? 1.f : 0.f;
        float m3 = (unsigned)(p0 + 3) < (unsigned)NTOT ? 1.f : 0.f;
        float* d0 = &sm[O_A4 + oc0 * ST + x0];
        float4 r;
        r.x = m0 * eluf(a0[0]); r.y = m1 * eluf(a0[1]); r.z = m2 * eluf(a0[2]); r.w = m3 * eluf(a0[3]);
        *(float4*)(d0) = r;
        r.x = m0 * eluf(a1[0]); r.y = m1 * eluf(a1[1]); r.z = m2 * eluf(a1[2]); r.w = m3 * eluf(a1[3]);
        *(float4*)(d0 + ST) = r;
        r.x = m0 * eluf(a2[0]); r.y = m1 * eluf(a2[1]); r.z = m2 * eluf(a2[2]); r.w = m3 * eluf(a2[3]);
        *(float4*)(d0 + 2 * ST) = r;
        r.x = m0 * eluf(a3[0]); r.y = m1 * eluf(a3[1]); r.z = m2 * eluf(a3[2]); r.w = m3 * eluf(a3[3]);
        *(float4*)(d0 + 3 * ST) = r;
    }
    // zero a4 tail slots (read by conv5 sliding window at the tile edge)
    for (int t = tid; t < 40; t += NTH) {
        float4 z = {0.f, 0.f, 0.f, 0.f};
        *(float4*)&sm[O_A4 + t * ST + 132] = z;
    }
    __syncthreads();

    // ---- conv5: 40->20, k3 pad1.  2 oc x 8 pos per task.  base o0+2 ----
    for (int t = tid; t < 10 * 17; t += NTH) {
        int ocp = t / 17, oct = t % 17;
        int x0 = oct * 8;
        int oc0 = ocp * 2;
        const float* wA = &sm[O_W5 + oc0 * 120];
        const float* wB = wA + 120;
        float bA = sm[O_B5 + oc0], bB = sm[O_B5 + oc0 + 1];
        float aA[8], aB[8];
        #pragma unroll
        for (int p = 0; p < 8; p++) { aA[p] = bA; aB[p] = bB; }
        #pragma unroll 4
        for (int ic = 0; ic < 40; ic++) {
            const float* ar = &sm[O_A4 + ic * ST + x0];
            float4 v0 = *(const float4*)(ar);
            float4 v1 = *(const float4*)(ar + 4);
            float4 v2 = *(const float4*)(ar + 8);
            float win[12] = {v0.x, v0.y, v0.z, v0.w, v1.x, v1.y, v1.z, v1.w,
                             v2.x, v2.y, v2.z, v2.w};
            #pragma unroll
            for (int k = 0; k < 3; k++) {
                float a = wA[ic * 3 + k], b = wB[ic * 3 + k];
                #pragma unroll
                for (int p = 0; p < 8; p++) {
                    aA[p] += a * win[p + k];
                    aB[p] += b * win[p + k];
                }
            }
        }
        float* dA = &sm[O_A5 + oc0 * ST + x0];
        float* dB = dA + ST;
        float4 rA0, rA1, rB0, rB1;
        rA0.x = eluf(aA[0]); rA0.y = eluf(aA[1]); rA0.z = eluf(aA[2]); rA0.w = eluf(aA[3]);
        rA1.x = eluf(aA[4]); rA1.y = eluf(aA[5]); rA1.z = eluf(aA[6]); rA1.w = eluf(aA[7]);
        rB0.x = eluf(aB[0]); rB0.y = eluf(aB[1]); rB0.z = eluf(aB[2]); rB0.w = eluf(aB[3]);
        rB1.x = eluf(aB[4]); rB1.y = eluf(aB[5]); rB1.z = eluf(aB[6]); rB1.w = eluf(aB[7]);
        *(float4*)(dA) = rA0; *(float4*)(dA + 4) = rA1;
        *(float4*)(dB) = rB0; *(float4*)(dB + 4) = rB1;
    }
    __syncthreads();

    // ---- conv6 + sigmoid + bias: beta_mult, base o0+2, width TW+2 ----
    for (int x = tid; x < TW + 2; x += NTH) {
        float acc = sm[O_B6];
        #pragma unroll
        for (int c = 0; c < 20; c++) acc += sm[O_W6 + c] * sm[O_A5 + c * ST + x];
        sm[O_BM + x] = 1.f / (1.f + __expf(-acc)) + 0.1f;
    }
    __syncthreads();

    // ---- WENO5 flux ----
    int j = o0 + tid;
    if (tid < TW && j < NOUT) {
        const float* U = &sm[O_UU + tid + 5];   // uu[j+1 .. j+6]
        float v0 = U[0], v1 = U[1], v2 = U[2], v3 = U[3], v4 = U[4], v5 = U[5];
        float m0 = sm[O_BM + tid];
        float m1 = sm[O_BM + tid + 1];
        float m2 = sm[O_BM + tid + 2];
        float e = e_p[0];
        float fluxp = weno_side(v1, v2, v3, v4, v5, m0, m1, m2, e);
        float fluxn = weno_side(v0, v1, v2, v3, v4, m0, m1, m2, e);
        out[j] = fluxp - fluxn;
    }
}

extern "C" void kernel_launch(void* const* d_in, const int* in_sizes, int n_in,
                              void* d_out, int out_size) {
    const float* uu = (const float*)d_in[0];
    const float* e  = (const float*)d_in[1];
    const float* w1 = (const float*)d_in[2];
    const float* b1 = (const float*)d_in[3];
    const float* w2 = (const float*)d_in[4];
    const float* b2 = (const float*)d_in[5];
    const float* w3 = (const float*)d_in[6];
    const float* b3 = (const float*)d_in[7];
    const float* w4 = (const float*)d_in[8];
    const float* b4 = (const float*)d_in[9];
    const float* w5 = (const float*)d_in[10];
    const float* b5 = (const float*)d_in[11];
    const float* w6 = (const float*)d_in[12];
    const float* b6 = (const float*)d_in[13];
    float* out = (float*)d_out;

    cudaFuncSetAttribute(weno_fused, cudaFuncAttributeMaxDynamicSharedMemorySize, SMEM_BYTES);
    int grid = (NOUT + TW - 1) / TW;
    weno_fused<<<grid, NTH, SMEM_BYTES>>>(uu, e, w1, b1, w2, b2, w3, b3, w4, b4,
                                          w5, b5, w6, b6, out);
}